// round 13
// baseline (speedup 1.0000x reference)
#include <cuda_runtime.h>
#include <cstdint>

// Math collapse (verified R8-R12): softmax over a size-1 axis == 1.0 exactly,
//   out[b,c,f] = sum_t x[b,t,f]     (context/W/b are dead inputs).
//
// Established experimentally:
//   - Pure contiguous streaming reads: ~8TB/s (R10 K1).
//   - 16MB output writes: ~8.5-8.9us (~1.85TB/s) via STG, __stcs, AND
//     cp.async.bulk individually, across 4 grid shapes -> path/shape invariant.
// Open question this kernel decides: is the write cap chip-wide-shared, or a
// per-SM per-engine cap? If per-engine, driving the LSU (STG) and the bulk
// async engine CONCURRENTLY on every SM doubles write bandwidth.
//
// Single fused launch: 256 CTAs; each reads a contiguous 128KB slice of x
// (64 rows of one b), publishes a partial, spins on its b's counter, then
// writes its 64KB output c-chunk via DUAL PATH: 32KB bulk-DMA + 32KB STG.

#define B_ 32
#define T_ 512
#define C_ 256
#define F_ 512

static constexpr int F4      = F_ / 4;      // 128 float4 per row
static constexpr int TPB     = 256;
static constexpr int NK      = 8;           // slices per b (read) == chunks per b (write)
static constexpr int T_SLICE = T_ / NK;     // 64 rows read per CTA
static constexpr int C_SLICE = C_ / NK;     // 32 rows written per CTA
static constexpr int REP     = 8;           // replicated rows in smem buf (16KB)
static constexpr int BULKB   = REP * F_ * 4;        // 16384 bytes per bulk copy

// Partials: [B][NK][F4] float4 (512KB). Flags zero-initialized at load and
// reset to zero by the last writer of each b at the end of every call.
__device__ float4 g_part[B_ * NK * F4];
__device__ int    g_cnt[B_];
__device__ int    g_done[B_];

__device__ __forceinline__ void f4add(float4& a, const float4& b) {
    a.x += b.x; a.y += b.y; a.z += b.z; a.w += b.w;
}

__device__ __forceinline__ uint32_t smem_u32(const void* p) {
    uint32_t a;
    asm("{ .reg .u64 t; cvta.to.shared.u64 t, %1; cvt.u32.u64 %0, t; }"
        : "=r"(a) : "l"(p));
    return a;
}

__global__ __launch_bounds__(TPB)
void fused_sum_bcast(const float* __restrict__ x, float* __restrict__ out) {
    const int b   = blockIdx.x >> 3;          // 0..31
    const int k   = blockIdx.x & 7;           // slice / chunk id
    const int f4l = threadIdx.x & (F4 - 1);   // 0..127
    const int h   = threadIdx.x >> 7;         // 0/1

    __shared__ __align__(128) float4 buf[REP * F4];   // 16KB

    // ---------------- Phase 1: contiguous streaming read + reduce ----------
    // CTA reads rows [k*64, k*64+64) of x[b] (128KB contiguous block).
    const float4* xb = reinterpret_cast<const float4*>(x)
                     + ((size_t)b * T_ + k * T_SLICE + h) * F4 + f4l;
    float4 acc = make_float4(0.f, 0.f, 0.f, 0.f);
#pragma unroll
    for (int g = 0; g < 4; ++g) {               // 4 groups of 8 batched loads
        float4 v0 = __ldg(&xb[(size_t)(g * 16 +  0) * F4]);
        float4 v1 = __ldg(&xb[(size_t)(g * 16 +  2) * F4]);
        float4 v2 = __ldg(&xb[(size_t)(g * 16 +  4) * F4]);
        float4 v3 = __ldg(&xb[(size_t)(g * 16 +  6) * F4]);
        float4 v4 = __ldg(&xb[(size_t)(g * 16 +  8) * F4]);
        float4 v5 = __ldg(&xb[(size_t)(g * 16 + 10) * F4]);
        float4 v6 = __ldg(&xb[(size_t)(g * 16 + 12) * F4]);
        float4 v7 = __ldg(&xb[(size_t)(g * 16 + 14) * F4]);
        f4add(v0, v4); f4add(v1, v5); f4add(v2, v6); f4add(v3, v7);
        f4add(v0, v2); f4add(v1, v3);
        f4add(v0, v1);
        f4add(acc, v0);
    }
    buf[threadIdx.x] = acc;
    __syncthreads();
    if (threadIdx.x < F4) {
        float4 tot = buf[threadIdx.x];
        f4add(tot, buf[threadIdx.x + F4]);
        g_part[((size_t)b * NK + k) * F4 + threadIdx.x] = tot;
        __threadfence();                        // publish partial
    }
    __syncthreads();
    if (threadIdx.x == 0) {
        atomicAdd(&g_cnt[b], 1);
        // ------------- Phase 2: wait for all 8 slices of this b -----------
        while (*(volatile int*)&g_cnt[b] < NK) __nanosleep(32);
        __threadfence();                        // acquire partials
    }
    __syncthreads();

    // ---------------- Phase 3: final sum + smem replication ---------------
    {
        const float4* pb = &g_part[((size_t)b * NK + h * (NK / 2)) * F4 + f4l];
        float4 s = make_float4(0.f, 0.f, 0.f, 0.f);
#pragma unroll
        for (int j = 0; j < NK / 2; ++j)
            f4add(s, pb[(size_t)j * F4]);
        buf[h * F4 + f4l] = s;
    }
    __syncthreads();
    if (threadIdx.x < F4) {
        float4 tot = buf[threadIdx.x];
        f4add(tot, buf[threadIdx.x + F4]);
        buf[threadIdx.x] = tot;                 // row 0 = final column sums
    }
    __syncthreads();
    {
        const float4 val = buf[f4l];
#pragma unroll
        for (int r = 1 + h; r < REP; r += 2)    // replicate rows 1..7
            buf[r * F4 + f4l] = val;
    }
    asm volatile("fence.proxy.async.shared::cta;" ::: "memory");
    __syncthreads();

    // ---------------- Phase 4: DUAL-PATH write of 64KB block --------------
    // Block = out[b, k*32 .. k*32+32, :]. Rows 0..15 via 2x 16KB bulk DMA
    // (async engine), rows 16..31 via per-thread __stcs (LSU) concurrently.
    float* blk = out + ((size_t)b * C_ + (size_t)k * C_SLICE) * F_;
    if (threadIdx.x == 0) {
        const uint32_t src = smem_u32(buf);
        char* dst = reinterpret_cast<char*>(blk);
        asm volatile("cp.async.bulk.global.shared::cta.bulk_group [%0], [%1], %2;"
                     :: "l"(dst), "r"(src), "n"(BULKB) : "memory");
        asm volatile("cp.async.bulk.global.shared::cta.bulk_group [%0], [%1], %2;"
                     :: "l"(dst + BULKB), "r"(src), "n"(BULKB) : "memory");
        asm volatile("cp.async.bulk.commit_group;" ::: "memory");
    }
    {
        float4* ob = reinterpret_cast<float4*>(blk) + 2 * REP * F4; // row 16
#pragma unroll
        for (int i = 0; i < (2 * REP * F4) / TPB; ++i) {            // 8 stores
            const int idx = (i << 8) + threadIdx.x;                 // 0..2047
            __stcs(&ob[idx], buf[idx & (F4 - 1)]);
        }
    }
    if (threadIdx.x == 0)
        asm volatile("cp.async.bulk.wait_group 0;" ::: "memory");
    __syncthreads();

    // ---------------- Phase 5: flag reset for the next graph replay -------
    if (threadIdx.x == 0) {
        atomicAdd(&g_done[b], 1);
        if (k == 0) {
            while (*(volatile int*)&g_done[b] < NK) __nanosleep(32);
            g_cnt[b]  = 0;
            g_done[b] = 0;
            __threadfence();
        }
    }
}

extern "C" void kernel_launch(void* const* d_in, const int* in_sizes, int n_in,
                              void* d_out, int out_size) {
    (void)in_sizes; (void)n_in; (void)out_size;
    const float* x = (const float*)d_in[0];   // [B,T,F]; context/W/b dead
    float* out = (float*)d_out;               // [B,C,F]
    // 256 CTAs x 256 threads: all CTAs guaranteed co-resident (<=8/SM by
    // threads, 16KB smem each), so the inter-CTA spin cannot deadlock.
    fused_sum_bcast<<<B_ * NK, TPB>>>(x, out);
}